// round 8
// baseline (speedup 1.0000x reference)
#include <cuda_runtime.h>
#include <math.h>

#define NB    32
#define NF    500
#define FEAT  256
#define COUT  2
#define CIN   2
#define KK    16
#define FRAME 160
#define OVL   40
#define NSAMP (NF * FRAME)          // 80000
#define NFILT (COUT * CIN * KK)     // 64

#define GAIN_A 0.69077552789821368f
#define SG     0.50118723362727224f
#define OMSG   0.49881276637272776f

// Per-frame filters: [(b*NF+f)*64 + cout*32 + cin*16 + k]
__device__ float g_w[(size_t)NB * NF * NFILT];
// W split hi/lo (tf32), transposed + interleaved: g_wil[k][n] = {hi, lo}
#define WILS 68
__device__ float2 g_wil[FEAT][WILS];

__device__ __forceinline__ unsigned f2tf(float x) {
    unsigned r;
    asm("cvt.rna.tf32.f32 %0, %1;" : "=r"(r) : "f"(x));
    return r;
}
__device__ __forceinline__ void mma8(float* d, const unsigned* a,
                                     const unsigned* b) {
    asm volatile(
        "mma.sync.aligned.m16n8k8.row.col.f32.tf32.tf32.f32 "
        "{%0,%1,%2,%3}, {%4,%5,%6,%7}, {%8,%9}, {%0,%1,%2,%3};"
        : "+f"(d[0]), "+f"(d[1]), "+f"(d[2]), "+f"(d[3])
        : "r"(a[0]), "r"(a[1]), "r"(a[2]), "r"(a[3]), "r"(b[0]), "r"(b[1]));
}

// ===========================================================================
// Pre-kernel: split ckw (64x256) into tf32 hi/lo, transposed to [k][n].
// ===========================================================================
__global__ void wsplit_kernel(const float* __restrict__ ckw) {
    int id = blockIdx.x * 256 + threadIdx.x;   // 64 blocks x 256 = 16384
    int n = id >> 8, k = id & 255;
    float v = ckw[(size_t)n * FEAT + k];
    unsigned hi = f2tf(v);
    float hif = __uint_as_float(hi);
    unsigned lo = f2tf(v - hif);
    g_wil[k][n] = make_float2(hif, __uint_as_float(lo));
}

// ===========================================================================
// Kernel A: 3xTF32 tensor-core filter GEMM + epilogue.
// Block = 64 rows x 64 cols, 256 threads (8 warps), warp tile 16x32.
// K = 256 -> 32 k8 steps; 3 mma per (m,n,k) tile (hi*hi, hi*lo, lo*hi).
// ===========================================================================
#define TBF  64
#define FSTR 260

__global__ void __launch_bounds__(256) filt_kernel(
    const float* __restrict__ feat,
    const float* __restrict__ ckb,
    const float* __restrict__ fgw,
    const float* __restrict__ fgb)
{
    extern __shared__ float sm[];
    float*  Fs  = sm;                                 // [64][260]
    float2* Wil = (float2*)(sm + TBF * FSTR);         // [256][68]
    float*  gg   = (float*)(Wil + FEAT * WILS);       // [64][2]
    float*  invn = gg + TBF * 2;
    float*  gain = invn + TBF * 2;
    float4* Fs4  = (float4*)Fs;

    int tid = threadIdx.x;
    int bf0 = blockIdx.x * TBF;

    // ---- stage F (coalesced) ----
    const float4* feat4 = (const float4*)feat;
    for (int i = tid; i < TBF * 64; i += 256) {
        int r = i >> 6, c = i & 63;
        Fs4[r * 65 + c] = feat4[(size_t)(bf0 + r) * 64 + c];
    }
    // ---- stage W hi/lo image (L2-hot) ----
    {
        const float4* src = (const float4*)g_wil;
        float4* dst = (float4*)Wil;
        for (int i = tid; i < FEAT * WILS / 2; i += 256)
            dst[i] = src[i];
    }
    __syncthreads();

    // ---- gain logits (scalar; reads Fs before it is overwritten) ----
    if (tid < TBF * 2) {
        int r = tid >> 1, c = tid & 1;
        const float4* fr = Fs4 + r * 65;
        const float4* gw = (const float4*)fgw + c * 64;
        float s = 0.f;
        #pragma unroll 4
        for (int q = 0; q < 64; ++q) {
            float4 a = fr[q];
            float4 b = __ldg(&gw[q]);
            s += a.x * b.x + a.y * b.y + a.z * b.z + a.w * b.w;
        }
        gg[tid] = s + __ldg(&fgb[c]);
    }

    // ---- 3xTF32 MMA mainloop ----
    int wid = tid >> 5, lane = tid & 31;
    int wr = (wid & 3) * 16;           // warp row offset
    int wn = (wid >> 2) * 32;          // warp col offset
    int g  = lane >> 2, tig = lane & 3;

    float acc[4][4];
    #pragma unroll
    for (int nt = 0; nt < 4; ++nt)
        #pragma unroll
        for (int i = 0; i < 4; ++i) acc[nt][i] = 0.f;

    const float* Ar0 = Fs + (wr + g) * FSTR + tig;
    const float* Ar1 = Fs + (wr + g + 8) * FSTR + tig;

    #pragma unroll 4
    for (int ks = 0; ks < 32; ++ks) {
        int k0 = ks * 8;
        float af[4] = {Ar0[k0], Ar1[k0], Ar0[k0 + 4], Ar1[k0 + 4]};
        unsigned ahi[4], alo[4];
        #pragma unroll
        for (int i = 0; i < 4; ++i) {
            ahi[i] = f2tf(af[i]);
            alo[i] = f2tf(af[i] - __uint_as_float(ahi[i]));
        }
        const float2* Bk0 = Wil + (k0 + tig) * WILS + wn + g;
        const float2* Bk1 = Wil + (k0 + tig + 4) * WILS + wn + g;
        #pragma unroll
        for (int nt = 0; nt < 4; ++nt) {
            float2 b0 = Bk0[nt * 8];
            float2 b1 = Bk1[nt * 8];
            unsigned bhi[2] = {__float_as_uint(b0.x), __float_as_uint(b1.x)};
            unsigned blo[2] = {__float_as_uint(b0.y), __float_as_uint(b1.y)};
            mma8(acc[nt], ahi, bhi);
            mma8(acc[nt], ahi, blo);
            mma8(acc[nt], alo, bhi);
        }
    }
    __syncthreads();                   // all Fs reads done -> safe to overwrite

    // ---- store raw (+bias) into reused Fs region, stride 68 ----
    float* raw = Fs;
    #pragma unroll
    for (int nt = 0; nt < 4; ++nt) {
        int col = wn + nt * 8 + 2 * tig;
        float b0 = __ldg(&ckb[col]), b1 = __ldg(&ckb[col + 1]);
        raw[(wr + g) * 68 + col]         = acc[nt][0] + b0;
        raw[(wr + g) * 68 + col + 1]     = acc[nt][1] + b1;
        raw[(wr + g + 8) * 68 + col]     = acc[nt][2] + b0;
        raw[(wr + g + 8) * 68 + col + 1] = acc[nt][3] + b1;
    }
    __syncthreads();

    // ---- per (row, cout) norm + gain ----
    if (tid < TBF * 2) {
        int r = tid >> 1, c = tid & 1;
        float ss = 0.f;
        #pragma unroll
        for (int i = 0; i < 32; ++i) {
            float v = raw[r * 68 + c * 32 + i];
            ss += v * v;
        }
        invn[tid] = 1.0f / (1e-6f + sqrtf(ss));
        gain[tid] = expf(GAIN_A * tanhf(gg[tid]));
    }
    __syncthreads();

    // ---- final scaled filters ----
    for (int idx = tid; idx < TBF * NFILT; idx += 256) {
        int r = idx >> 6, o = idx & 63;
        int co = o >> 5;
        float v = SG * raw[r * 68 + o] * invn[r * 2 + co];
        if ((o & 15) == 7) v += OMSG;              // identity tap k=7
        g_w[(size_t)(bf0 + r) * NFILT + o] = v * gain[r * 2 + co];
    }
}

// ===========================================================================
// Kernel B: R7 conv (best known): FPB=5, 160 threads, lb(160,8);
// predicated tail reusing the head register window.
// ===========================================================================
#define FPB  5
#define NEED (FPB * FRAME + 16)      // 816
#define XPAD 824

__global__ void __launch_bounds__(FPB * 32, 8) conv_kernel(
    const float* __restrict__ x,     // (B, CIN, NSAMP)
    const float* __restrict__ owin,  // (40,)
    float* __restrict__ out)         // (B, COUT, NSAMP)
{
    __shared__ __align__(16) float xs[CIN][XPAD];
    __shared__ __align__(16) float wsm[FPB + 1][NFILT];
    __shared__ __align__(16) float ob[FPB][COUT][FRAME];
    __shared__ float w1s[OVL], w2s[OVL];

    const int NT = FPB * 32;
    int f0 = blockIdx.x * FPB;
    int b  = blockIdx.y;
    int tid  = threadIdx.x;
    int lane = tid & 31;
    int w    = tid >> 5;

    const float* xb = x + (size_t)b * CIN * NSAMP;
    if (f0 == 0) {
        if (tid < 16) { xs[0][tid] = 0.f; xs[1][tid] = 0.f; }
        const int N4 = (NEED - 16) / 4;
        for (int i = tid; i < CIN * N4; i += NT) {
            int ci = i / N4, q = i - ci * N4;
            ((float4*)(xs[ci] + 16))[q] =
                ((const float4*)(xb + (size_t)ci * NSAMP))[q];
        }
    } else {
        int base = f0 * FRAME - 16;
        const int N4 = NEED / 4;
        for (int i = tid; i < CIN * N4; i += NT) {
            int ci = i / N4, q = i - ci * N4;
            ((float4*)xs[ci])[q] =
                ((const float4*)(xb + (size_t)ci * NSAMP + base))[q];
        }
    }
    for (int i = tid; i < (FPB + 1) * NFILT; i += NT) {
        int fi = f0 - 1 + (i >> 6);
        wsm[0][i] = (fi >= 0) ? g_w[((size_t)b * NF + fi) * NFILT + (i & 63)]
                              : 0.f;
    }
    if (tid < OVL) {
        w2s[tid] = owin[tid];
        w1s[tid] = owin[OVL - 1 - tid];
    }
    __syncthreads();

    int j0 = 5 * lane;
    int sb = w * FRAME + 16;

    float a0[5] = {0,0,0,0,0}, a1[5] = {0,0,0,0,0};
    float p0[5] = {0,0,0,0,0}, p1[5] = {0,0,0,0,0};

    const float4* wc = (const float4*)wsm[w + 1];
    const float4* wp = (const float4*)wsm[w];

    #pragma unroll
    for (int ci = 0; ci < CIN; ++ci) {
        float xw[20];
        #pragma unroll
        for (int i = 0; i < 20; ++i)
            xw[i] = xs[ci][sb + j0 - 15 + i];

        #pragma unroll
        for (int kc = 0; kc < 4; ++kc) {
            float4 c0 = wc[ci * 4 + kc];
            float4 c1 = wc[8 + ci * 4 + kc];
            float wk0[4] = {c0.x, c0.y, c0.z, c0.w};
            float wk1[4] = {c1.x, c1.y, c1.z, c1.w};
            #pragma unroll
            for (int kk = 0; kk < 4; ++kk) {
                int k = 4 * kc + kk;
                #pragma unroll
                for (int m = 0; m < 5; ++m) {
                    float xv = xw[m + 15 - k];
                    a0[m] = fmaf(wk0[kk], xv, a0[m]);
                    a1[m] = fmaf(wk1[kk], xv, a1[m]);
                }
            }
        }
        if (lane < 8) {
            #pragma unroll
            for (int kc = 0; kc < 4; ++kc) {
                float4 c0 = wp[ci * 4 + kc];
                float4 c1 = wp[8 + ci * 4 + kc];
                float wk0[4] = {c0.x, c0.y, c0.z, c0.w};
                float wk1[4] = {c1.x, c1.y, c1.z, c1.w};
                #pragma unroll
                for (int kk = 0; kk < 4; ++kk) {
                    int k = 4 * kc + kk;
                    #pragma unroll
                    for (int m = 0; m < 5; ++m) {
                        float xv = xw[m + 15 - k];
                        p0[m] = fmaf(wk0[kk], xv, p0[m]);
                        p1[m] = fmaf(wk1[kk], xv, p1[m]);
                    }
                }
            }
        }
    }

    if (lane < 8) {
        #pragma unroll
        for (int m = 0; m < 5; ++m) {
            int j = j0 + m;
            ob[w][0][j] = w1s[j] * a0[m] + w2s[j] * p0[m];
            ob[w][1][j] = w1s[j] * a1[m] + w2s[j] * p1[m];
        }
    } else {
        #pragma unroll
        for (int m = 0; m < 5; ++m) {
            int j = j0 + m;
            ob[w][0][j] = a0[m];
            ob[w][1][j] = a1[m];
        }
    }
    __syncwarp();

    int f = f0 + w;
    #pragma unroll
    for (int co = 0; co < COUT; ++co) {
        float4* op = (float4*)(out + (size_t)b * COUT * NSAMP
                               + (size_t)co * NSAMP + (size_t)f * FRAME);
        const float4* obp = (const float4*)ob[w][co];
        #pragma unroll
        for (int i = lane; i < FRAME / 4; i += 32)
            op[i] = obp[i];
    }
}

extern "C" void kernel_launch(void* const* d_in, const int* in_sizes, int n_in,
                              void* d_out, int out_size)
{
    const float* x    = (const float*)d_in[0];
    const float* feat = (const float*)d_in[1];
    const float* ckw  = (const float*)d_in[2];
    const float* ckb  = (const float*)d_in[3];
    const float* fgw  = (const float*)d_in[4];
    const float* fgb  = (const float*)d_in[5];
    const float* ow   = (const float*)d_in[6];
    float* out = (float*)d_out;

    // filt smem: Fs 64*260 + Wil 256*68*2 + 3*128 floats
    int smem = (TBF * FSTR + FEAT * WILS * 2 + 3 * TBF * 2) * (int)sizeof(float);
    static int configured = 0;
    if (!configured) {
        cudaFuncSetAttribute(filt_kernel,
                             cudaFuncAttributeMaxDynamicSharedMemorySize, smem);
        configured = 1;
    }

    wsplit_kernel<<<64, 256>>>(ckw);
    filt_kernel<<<NB * NF / TBF, 256, smem>>>(feat, ckb, fgw, fgb);
    conv_kernel<<<dim3(NF / FPB, NB), FPB * 32>>>(x, ow, out);
}